// round 12
// baseline (speedup 1.0000x reference)
#include <cuda_runtime.h>
#include <cuda_bf16.h>
#include <float.h>
#include <stdint.h>

// Fixed problem shape
#define KC      512         // codebook size
#define DC      64          // code dim
#define HWC     4096        // H*W
#define NC      131072      // B*H*W
#define TPB     256         // 8 warps
#define PIX     128         // pixels per tile
#define NTILES  (NC/PIX)    // 1024 tiles
#define GRIDP   256         // 2 CTAs/SM; 4 tiles per CTA, balanced
#define CAP     24          // candidate list capacity per pixel
#define EPITCH  72          // bf16 row pitch (pad: 144B = 36 banks, conflict-free)

// smem layout (bytes)
#define OFF_ECB   0                         // bf16 [512][72]      73728
#define OFF_ABF   (OFF_ECB + KC*EPITCH*2)   // bf16 [128][72]      18432
#define OFF_EN    (OFF_ABF + PIX*EPITCH*2)  // float[512]           2048
#define OFF_FN    (OFF_EN + KC*4)           // float[128]            512
#define OFF_SLK   (OFF_FN + PIX*4)          // float[128]            512
#define OFF_MIN   (OFF_SLK + PIX*4)         // float[128]            512
#define OFF_THR   (OFF_MIN + PIX*4)         // float[128]            512
#define OFF_CNT   (OFF_THR + PIX*4)         // int[128]              512
#define OFF_CL    (OFF_CNT + PIX*4)         // int16[128][24]       6144
#define OFF_RED   (OFF_CL + PIX*CAP*2)      // float[256]           1024
#define SMEM_BYTES (OFF_RED + TPB*4)

__device__ float    g_part[NTILES];
__device__ unsigned g_done;

__device__ __forceinline__ void mma_bf16(float c[4], const unsigned a[4],
                                         unsigned b0, unsigned b1) {
    asm volatile(
        "mma.sync.aligned.m16n8k16.row.col.f32.bf16.bf16.f32 "
        "{%0,%1,%2,%3}, {%4,%5,%6,%7}, {%8,%9}, {%0,%1,%2,%3};"
        : "+f"(c[0]), "+f"(c[1]), "+f"(c[2]), "+f"(c[3])
        : "r"(a[0]), "r"(a[1]), "r"(a[2]), "r"(a[3]), "r"(b0), "r"(b1));
}

__global__ __launch_bounds__(TPB, 2)
void vq_kernel(const float* __restrict__ latents,
               const float* __restrict__ embedding,
               float* __restrict__ out,
               float* __restrict__ loss_out) {
    extern __shared__ char smem[];
    __nv_bfloat16* Ecb = (__nv_bfloat16*)(smem + OFF_ECB);
    __nv_bfloat16* Abf = (__nv_bfloat16*)(smem + OFF_ABF);
    float*   enS   = (float*)(smem + OFF_EN);
    float*   fnS   = (float*)(smem + OFF_FN);
    float*   slkS  = (float*)(smem + OFF_SLK);
    float*   minvS = (float*)(smem + OFF_MIN);
    float*   thrS  = (float*)(smem + OFF_THR);
    int*     ccnt  = (int*)(smem + OFF_CNT);
    short*   clist = (short*)(smem + OFF_CL);
    float*   red   = (float*)(smem + OFF_RED);

    const int tid  = threadIdx.x;
    const int wid  = tid >> 5;
    const int lane = tid & 31;
    const int g    = lane >> 2;       // group id (mma row/col group)
    const int tig  = lane & 3;        // thread-in-group

    // ---- once per CTA: bf16 codebook + exact reference enorm ----
    for (int i = tid; i < KC * DC; i += TPB) {
        int k = i >> 6, d = i & 63;
        Ecb[k * EPITCH + d] = __float2bfloat16_rn(embedding[i]);
    }
    #pragma unroll
    for (int kk = 0; kk < 2; ++kk) {
        int k = tid + kk * TPB;
        const float* er = embedding + (size_t)k * DC;
        float s = 0.0f;
        #pragma unroll
        for (int d = 0; d < DC; ++d)
            s = __fadd_rn(s, __fmul_rn(er[d], er[d]));
        enS[k] = s;
    }
    __syncthreads();

    // ---- persistent tile loop: 4 tiles of 128 pixels per CTA ----
    for (int tile = blockIdx.x; tile < NTILES; tile += GRIDP) {

        // ---- phase 0: stage A (bf16), fnorm (exact), error bound ----
        if (tid < PIX) {
            const int P  = tile * PIX + tid;
            const int b  = P >> 12;
            const int hw = P & (HWC - 1);
            const float* lat = latents + (size_t)b * DC * HWC + hw;
            float fn = 0.0f, bnd = 0.0f;
            #pragma unroll
            for (int d = 0; d < DC; ++d) {
                float f = lat[d * HWC];
                __nv_bfloat16 fb = __float2bfloat16_rn(f);
                Abf[tid * EPITCH + d] = fb;
                fn  = __fadd_rn(fn, __fmul_rn(f, f));
                // |f|*max_bf16_err(e) + max|bf(e)|*|f - bf(f)|
                bnd += fabsf(f) * 4.0e-6f + 1.96e-3f * fabsf(f - __bfloat162float(fb));
            }
            fnS[tid]  = fn;
            // threshold slack: 4*B_dot (both sides, dot doubled) + fl-rounding cover
            slkS[tid] = fmaf(5.0f, bnd, 1.5e-4f);
        }
        __syncthreads();

        // ---- load A fragments for this warp's 16 rows (reused both passes) ----
        const int r0 = wid * 16 + g;
        const int r1 = r0 + 8;
        unsigned afr[4][4];
        #pragma unroll
        for (int ks = 0; ks < 4; ++ks) {
            afr[ks][0] = *(const unsigned*)(Abf + r0 * EPITCH + 16 * ks + 2 * tig);
            afr[ks][1] = *(const unsigned*)(Abf + r1 * EPITCH + 16 * ks + 2 * tig);
            afr[ks][2] = *(const unsigned*)(Abf + r0 * EPITCH + 16 * ks + 8 + 2 * tig);
            afr[ks][3] = *(const unsigned*)(Abf + r1 * EPITCH + 16 * ks + 8 + 2 * tig);
        }

        // ---- phase 1: GEMM pass, per-pixel min of screening score ----
        float rm0 = FLT_MAX, rm1 = FLT_MAX;
        #pragma unroll 4
        for (int nb = 0; nb < KC / 8; ++nb) {
            const int cb = nb * 8;
            const __nv_bfloat16* brow = Ecb + (cb + g) * EPITCH;
            float c[4] = {0.f, 0.f, 0.f, 0.f};
            #pragma unroll
            for (int ks = 0; ks < 4; ++ks) {
                unsigned b0 = *(const unsigned*)(brow + 16 * ks + 2 * tig);
                unsigned b1 = *(const unsigned*)(brow + 16 * ks + 8 + 2 * tig);
                mma_bf16(c, afr[ks], b0, b1);
            }
            float en0 = enS[cb + 2 * tig];
            float en1 = enS[cb + 2 * tig + 1];
            float s0 = fmaf(-2.0f, c[0], en0);
            float s1 = fmaf(-2.0f, c[1], en1);
            float s2 = fmaf(-2.0f, c[2], en0);
            float s3 = fmaf(-2.0f, c[3], en1);
            rm0 = fminf(rm0, fminf(s0, s1));
            rm1 = fminf(rm1, fminf(s2, s3));
        }
        rm0 = fminf(rm0, __shfl_xor_sync(0xffffffffu, rm0, 1));
        rm0 = fminf(rm0, __shfl_xor_sync(0xffffffffu, rm0, 2));
        rm1 = fminf(rm1, __shfl_xor_sync(0xffffffffu, rm1, 1));
        rm1 = fminf(rm1, __shfl_xor_sync(0xffffffffu, rm1, 2));
        minvS[r0] = rm0;
        minvS[r1] = rm1;
        __syncthreads();

        if (tid < PIX) {
            thrS[tid] = minvS[tid] + slkS[tid];
            ccnt[tid] = 0;
        }
        __syncthreads();

        // ---- phase 2: GEMM pass, collect candidates <= threshold ----
        {
            const float t0 = thrS[r0];
            const float t1 = thrS[r1];
            #pragma unroll 4
            for (int nb = 0; nb < KC / 8; ++nb) {
                const int cb = nb * 8;
                const __nv_bfloat16* brow = Ecb + (cb + g) * EPITCH;
                float c[4] = {0.f, 0.f, 0.f, 0.f};
                #pragma unroll
                for (int ks = 0; ks < 4; ++ks) {
                    unsigned b0 = *(const unsigned*)(brow + 16 * ks + 2 * tig);
                    unsigned b1 = *(const unsigned*)(brow + 16 * ks + 8 + 2 * tig);
                    mma_bf16(c, afr[ks], b0, b1);
                }
                float en0 = enS[cb + 2 * tig];
                float en1 = enS[cb + 2 * tig + 1];
                float s0 = fmaf(-2.0f, c[0], en0);
                float s1 = fmaf(-2.0f, c[1], en1);
                float s2 = fmaf(-2.0f, c[2], en0);
                float s3 = fmaf(-2.0f, c[3], en1);
                if (s0 <= t0) { int p_ = atomicAdd(&ccnt[r0], 1); if (p_ < CAP) clist[r0 * CAP + p_] = (short)(cb + 2 * tig); }
                if (s1 <= t0) { int p_ = atomicAdd(&ccnt[r0], 1); if (p_ < CAP) clist[r0 * CAP + p_] = (short)(cb + 2 * tig + 1); }
                if (s2 <= t1) { int p_ = atomicAdd(&ccnt[r1], 1); if (p_ < CAP) clist[r1 * CAP + p_] = (short)(cb + 2 * tig); }
                if (s3 <= t1) { int p_ = atomicAdd(&ccnt[r1], 1); if (p_ < CAP) clist[r1 * CAP + p_] = (short)(cb + 2 * tig + 1); }
            }
        }
        __syncthreads();

        // ---- phase 3: exact reference-arithmetic re-check + output ----
        float ldist = 0.0f;
        if (tid < PIX) {
            const int P  = tile * PIX + tid;
            const int b  = P >> 12;
            const int hw = P & (HWC - 1);
            const float* lat = latents + (size_t)b * DC * HWC + hw;
            const float  fn  = fnS[tid];
            const int    cc  = ccnt[tid];

            float best  = FLT_MAX;
            int   bestk = KC;

            if (cc <= CAP) {
                for (int i = 0; i < cc; ++i) {
                    int k = clist[tid * CAP + i];
                    const float* er = embedding + (size_t)k * DC;
                    float dot = 0.0f;
                    #pragma unroll
                    for (int d = 0; d < DC; ++d)
                        dot = fmaf(lat[d * HWC], er[d], dot);     // sequential FMA chain
                    float r = __fsub_rn(__fadd_rn(fn, enS[k]), __fmul_rn(2.0f, dot));
                    if (r < best || (r == best && k < bestk)) { best = r; bestk = k; }
                }
            } else {
                // overflow fallback: full exact scan (correct by construction)
                for (int k = 0; k < KC; ++k) {
                    const float* er = embedding + (size_t)k * DC;
                    float dot = 0.0f;
                    #pragma unroll
                    for (int d = 0; d < DC; ++d)
                        dot = fmaf(lat[d * HWC], er[d], dot);
                    float r = __fsub_rn(__fadd_rn(fn, enS[k]), __fmul_rn(2.0f, dot));
                    if (r < best) { best = r; bestk = k; }         // ascending k
                }
            }

            // STE output + per-pixel loss (identical ops to rel_err=0.0 lineage)
            const float* er = embedding + (size_t)bestk * DC;
            float* outp = out + (size_t)b * DC * HWC + hw;
            #pragma unroll
            for (int d = 0; d < DC; ++d) {
                float f  = lat[d * HWC];
                float dq = __fsub_rn(er[d], f);
                ldist = __fadd_rn(ldist, __fmul_rn(dq, dq));
                outp[d * HWC] = __fadd_rn(f, dq);
            }
        }

        // ---- per-tile deterministic tree reduce -> g_part[tile] ----
        red[tid] = ldist;
        __syncthreads();
        #pragma unroll
        for (int s = TPB / 2; s > 0; s >>= 1) {
            if (tid < s) red[tid] += red[tid + s];
            __syncthreads();
        }
        if (tid == 0) g_part[tile] = red[0];
        __syncthreads();
    }

    // ---- grid finalize: last CTA reduces the 1024 tile partials ----
    __shared__ unsigned s_last;
    __threadfence();
    if (tid == 0) s_last = (atomicAdd(&g_done, 1u) == GRIDP - 1u);
    __syncthreads();

    if (s_last) {
        red[tid] = (g_part[tid] + g_part[tid + 256])
                 + (g_part[tid + 512] + g_part[tid + 768]);
        __syncthreads();
        #pragma unroll
        for (int s = TPB / 2; s > 0; s >>= 1) {
            if (tid < s) red[tid] += red[tid + s];
            __syncthreads();
        }
        if (tid == 0) {
            float m = red[0] / 8388608.0f;                   // exact /2^23
            *loss_out = __fadd_rn(__fmul_rn(m, 0.25f), m);   // fl(0.25m)+m
            g_done = 0;                                      // reset for replay
        }
    }
}

extern "C" void kernel_launch(void* const* d_in, const int* in_sizes, int n_in,
                              void* d_out, int out_size) {
    const float* latents   = (const float*)d_in[0];   // [32,64,64,64] fp32
    const float* embedding = (const float*)d_in[1];   // [512,64] fp32
    float* out  = (float*)d_out;                      // tensor, then loss scalar
    float* loss = out + (out_size - 1);

    cudaFuncSetAttribute(vq_kernel, cudaFuncAttributeMaxDynamicSharedMemorySize, SMEM_BYTES);
    vq_kernel<<<GRIDP, TPB, SMEM_BYTES>>>(latents, embedding, out, loss);
}

// round 13
// speedup vs baseline: 1.2637x; 1.2637x over previous
#include <cuda_runtime.h>
#include <cuda_bf16.h>
#include <float.h>
#include <stdint.h>

// Fixed problem shape
#define KC      512         // codebook size
#define DC      64          // code dim
#define HWC     4096        // H*W
#define NC      131072      // B*H*W
#define TPB     256         // 8 warps
#define PIX     128         // pixels per tile
#define NTILES  (NC/PIX)    // 1024 tiles
#define GRIDP   256         // 2 CTAs/SM target; dynamic tile stealing
#define EPITCH  72          // bf16 codebook pitch (conflict-free B frags)
#define FPITCH  66          // fp32 latent pitch (even: float2-aligned; 2-way max)
#define WLCAP   768         // worklist capacity (pairs per tile)

// smem layout (bytes)
#define OFF_ECB 0                           // bf16 [512][72]   73728
#define OFF_F32 (OFF_ECB + KC*EPITCH*2)     // fp32 [128][66]   33792
#define OFF_EN  (OFF_F32 + PIX*FPITCH*4)    // float[512]        2048
#define OFF_FN  (OFF_EN + KC*4)             // float[128]         512
#define OFF_SLK (OFF_FN + PIX*4)            // float[128]         512
#define OFF_THR (OFF_SLK + PIX*4)           // float[128]         512
#define OFF_BST (OFF_THR + PIX*4)           // u64  [128]        1024
#define OFF_WL  (OFF_BST + PIX*8)           // u32  [768]        3072 (red overlays)
#define OFF_CNT (OFF_WL + WLCAP*4)          // int + pad           16
#define SMEM_BYTES (OFF_CNT + 16)           // 115232 -> fits 2/SM

__device__ float    g_part[NTILES];
__device__ unsigned g_done;     // zero-init; finalizer resets
__device__ unsigned g_tile;     // dynamic tile counter; finalizer resets

__device__ __forceinline__ void mma_bf16(float c[4], const unsigned a[4],
                                         unsigned b0, unsigned b1) {
    asm volatile(
        "mma.sync.aligned.m16n8k16.row.col.f32.bf16.bf16.f32 "
        "{%0,%1,%2,%3}, {%4,%5,%6,%7}, {%8,%9}, {%0,%1,%2,%3};"
        : "+f"(c[0]), "+f"(c[1]), "+f"(c[2]), "+f"(c[3])
        : "r"(a[0]), "r"(a[1]), "r"(a[2]), "r"(a[3]), "r"(b0), "r"(b1));
}

__device__ __forceinline__ unsigned pack_bf2(float2 p) {
    __nv_bfloat162 h = __float22bfloat162_rn(p);
    return *reinterpret_cast<unsigned*>(&h);
}

__global__ __launch_bounds__(TPB, 2)
void vq_kernel(const float* __restrict__ latents,
               const float* __restrict__ embedding,
               float* __restrict__ out,
               float* __restrict__ loss_out) {
    extern __shared__ char smem[];
    __nv_bfloat16* Ecb = (__nv_bfloat16*)(smem + OFF_ECB);
    float* F32  = (float*)(smem + OFF_F32);
    float* enS  = (float*)(smem + OFF_EN);
    float* fnS  = (float*)(smem + OFF_FN);
    float* slkS = (float*)(smem + OFF_SLK);
    float* thrS = (float*)(smem + OFF_THR);
    unsigned long long* bestS = (unsigned long long*)(smem + OFF_BST);
    unsigned* wl   = (unsigned*)(smem + OFF_WL);
    int*      wcnt = (int*)(smem + OFF_CNT);
    float*    red  = (float*)(smem + OFF_WL);   // overlay; used after pairs done

    const int tid  = threadIdx.x;
    const int wid  = tid >> 5;
    const int lane = tid & 31;
    const int g    = lane >> 2;
    const int tig  = lane & 3;

    // ---- once per CTA: bf16 codebook + exact reference enorm ----
    for (int i = tid; i < KC * DC; i += TPB) {
        int k = i >> 6, d = i & 63;
        Ecb[k * EPITCH + d] = __float2bfloat16_rn(embedding[i]);
    }
    #pragma unroll
    for (int kk = 0; kk < 2; ++kk) {
        int k = tid + kk * TPB;
        const float* er = embedding + (size_t)k * DC;
        float s = 0.0f;
        #pragma unroll
        for (int d = 0; d < DC; ++d)
            s = __fadd_rn(s, __fmul_rn(er[d], er[d]));
        enS[k] = s;
    }
    __syncthreads();

    __shared__ int s_tile;

    // ---- dynamic tile loop ----
    while (true) {
        if (tid == 0) s_tile = (int)atomicAdd(&g_tile, 1u);
        __syncthreads();
        const int tile = s_tile;
        if (tile >= NTILES) break;

        // ---- phase 0: stage fp32 latents to smem, fnorm, slack ----
        if (tid < PIX) {
            const int P  = tile * PIX + tid;
            const int b  = P >> 12;
            const int hw = P & (HWC - 1);
            const float* lat = latents + (size_t)b * DC * HWC + hw;
            float* fr = F32 + tid * FPITCH;
            float fn = 0.0f, bnd = 0.0f;
            #pragma unroll
            for (int d = 0; d < DC; ++d) {
                float f = lat[d * HWC];
                fr[d] = f;
                fn = __fadd_rn(fn, __fmul_rn(f, f));
                float fb = __bfloat162float(__float2bfloat16_rn(f));
                bnd += fabsf(f) * 4.0e-6f + 1.96e-3f * fabsf(f - fb);
            }
            fnS[tid]  = fn;
            slkS[tid] = fmaf(5.0f, bnd, 1.5e-4f);
            bestS[tid] = 0xFFFFFFFFFFFFFFFFull;
        }
        if (tid == 0) *wcnt = 0;
        __syncthreads();

        // ---- A fragments for this warp's 16 rows (cvt fp32->bf16 on the fly) ----
        const int r0 = wid * 16 + g;
        const int r1 = r0 + 8;
        unsigned afr[4][4];
        #pragma unroll
        for (int ks = 0; ks < 4; ++ks) {
            afr[ks][0] = pack_bf2(*(const float2*)(F32 + r0 * FPITCH + 16 * ks + 2 * tig));
            afr[ks][1] = pack_bf2(*(const float2*)(F32 + r1 * FPITCH + 16 * ks + 2 * tig));
            afr[ks][2] = pack_bf2(*(const float2*)(F32 + r0 * FPITCH + 16 * ks + 8 + 2 * tig));
            afr[ks][3] = pack_bf2(*(const float2*)(F32 + r1 * FPITCH + 16 * ks + 8 + 2 * tig));
        }

        // ---- phase 1: GEMM pass, per-pixel screening min ----
        float rm0 = FLT_MAX, rm1 = FLT_MAX;
        #pragma unroll 4
        for (int nb = 0; nb < KC / 8; ++nb) {
            const int cb = nb * 8;
            const __nv_bfloat16* brow = Ecb + (cb + g) * EPITCH;
            float c[4] = {0.f, 0.f, 0.f, 0.f};
            #pragma unroll
            for (int ks = 0; ks < 4; ++ks) {
                unsigned b0 = *(const unsigned*)(brow + 16 * ks + 2 * tig);
                unsigned b1 = *(const unsigned*)(brow + 16 * ks + 8 + 2 * tig);
                mma_bf16(c, afr[ks], b0, b1);
            }
            float en0 = enS[cb + 2 * tig];
            float en1 = enS[cb + 2 * tig + 1];
            rm0 = fminf(rm0, fminf(fmaf(-2.0f, c[0], en0), fmaf(-2.0f, c[1], en1)));
            rm1 = fminf(rm1, fminf(fmaf(-2.0f, c[2], en0), fmaf(-2.0f, c[3], en1)));
        }
        rm0 = fminf(rm0, __shfl_xor_sync(0xffffffffu, rm0, 1));
        rm0 = fminf(rm0, __shfl_xor_sync(0xffffffffu, rm0, 2));
        rm1 = fminf(rm1, __shfl_xor_sync(0xffffffffu, rm1, 1));
        rm1 = fminf(rm1, __shfl_xor_sync(0xffffffffu, rm1, 2));
        if (tig == 0) {
            thrS[r0] = rm0;     // min; slack added below
            thrS[r1] = rm1;
        }
        __syncthreads();
        if (tid < PIX) thrS[tid] = thrS[tid] + slkS[tid];
        __syncthreads();

        // ---- phase 2: GEMM pass, collect candidate (pixel,k) pairs ----
        {
            const float t0 = thrS[r0];
            const float t1 = thrS[r1];
            #pragma unroll 4
            for (int nb = 0; nb < KC / 8; ++nb) {
                const int cb = nb * 8;
                const __nv_bfloat16* brow = Ecb + (cb + g) * EPITCH;
                float c[4] = {0.f, 0.f, 0.f, 0.f};
                #pragma unroll
                for (int ks = 0; ks < 4; ++ks) {
                    unsigned b0 = *(const unsigned*)(brow + 16 * ks + 2 * tig);
                    unsigned b1 = *(const unsigned*)(brow + 16 * ks + 8 + 2 * tig);
                    mma_bf16(c, afr[ks], b0, b1);
                }
                float en0 = enS[cb + 2 * tig];
                float en1 = enS[cb + 2 * tig + 1];
                float s0 = fmaf(-2.0f, c[0], en0);
                float s1 = fmaf(-2.0f, c[1], en1);
                float s2 = fmaf(-2.0f, c[2], en0);
                float s3 = fmaf(-2.0f, c[3], en1);
                if (s0 <= t0) { int p_ = atomicAdd(wcnt, 1); if (p_ < WLCAP) wl[p_] = ((unsigned)r0 << 16) | (unsigned)(cb + 2 * tig); }
                if (s1 <= t0) { int p_ = atomicAdd(wcnt, 1); if (p_ < WLCAP) wl[p_] = ((unsigned)r0 << 16) | (unsigned)(cb + 2 * tig + 1); }
                if (s2 <= t1) { int p_ = atomicAdd(wcnt, 1); if (p_ < WLCAP) wl[p_] = ((unsigned)r1 << 16) | (unsigned)(cb + 2 * tig); }
                if (s3 <= t1) { int p_ = atomicAdd(wcnt, 1); if (p_ < WLCAP) wl[p_] = ((unsigned)r1 << 16) | (unsigned)(cb + 2 * tig + 1); }
            }
        }
        __syncthreads();

        // ---- phase 3: parallel exact recheck over all pairs ----
        const int  nw  = *wcnt;
        const bool ovf = (nw > WLCAP);
        if (!ovf) {
            for (int i = tid; i < nw; i += TPB) {
                unsigned e = wl[i];
                int pix = (int)(e >> 16);
                int k   = (int)(e & 0xFFFFu);
                const float*  fr  = F32 + pix * FPITCH;
                const float4* er4 = (const float4*)(embedding + (size_t)k * DC);
                float dot = 0.0f;
                #pragma unroll
                for (int q = 0; q < 16; ++q) {
                    float4 ev = __ldg(er4 + q);
                    dot = fmaf(fr[4 * q + 0], ev.x, dot);   // sequential ref chain
                    dot = fmaf(fr[4 * q + 1], ev.y, dot);
                    dot = fmaf(fr[4 * q + 2], ev.z, dot);
                    dot = fmaf(fr[4 * q + 3], ev.w, dot);
                }
                float r = __fsub_rn(__fadd_rn(fnS[pix], enS[k]), __fmul_rn(2.0f, dot));
                unsigned rb = __float_as_uint(r);
                rb ^= (rb >> 31) ? 0xFFFFFFFFu : 0x80000000u;   // order-preserving
                unsigned long long key = ((unsigned long long)rb << 32) | (unsigned)k;
                atomicMin(&bestS[pix], key);                    // value, then min k
            }
        }
        __syncthreads();

        // ---- phase 4: per-pixel winner, STE output, loss partial ----
        float ldist = 0.0f;
        if (tid < PIX) {
            const float* fr = F32 + tid * FPITCH;
            const float  fn = fnS[tid];
            int bestk;
            if (!ovf) {
                bestk = (int)(unsigned)(bestS[tid] & 0xFFFFFFFFull);
            } else {
                // overflow fallback: full exact scan (correct by construction)
                float best = FLT_MAX; bestk = 0;
                for (int k = 0; k < KC; ++k) {
                    const float4* er4 = (const float4*)(embedding + (size_t)k * DC);
                    float dot = 0.0f;
                    #pragma unroll
                    for (int q = 0; q < 16; ++q) {
                        float4 ev = __ldg(er4 + q);
                        dot = fmaf(fr[4 * q + 0], ev.x, dot);
                        dot = fmaf(fr[4 * q + 1], ev.y, dot);
                        dot = fmaf(fr[4 * q + 2], ev.z, dot);
                        dot = fmaf(fr[4 * q + 3], ev.w, dot);
                    }
                    float r = __fsub_rn(__fadd_rn(fn, enS[k]), __fmul_rn(2.0f, dot));
                    if (r < best) { best = r; bestk = k; }      // ascending k
                }
            }

            const int P  = tile * PIX + tid;
            const int b  = P >> 12;
            const int hw = P & (HWC - 1);
            float* outp = out + (size_t)b * DC * HWC + hw;
            const float4* er4 = (const float4*)(embedding + (size_t)bestk * DC);
            #pragma unroll
            for (int q = 0; q < 16; ++q) {
                float4 ev = __ldg(er4 + q);
                float f0 = fr[4 * q + 0], f1 = fr[4 * q + 1];
                float f2 = fr[4 * q + 2], f3 = fr[4 * q + 3];
                float d0 = __fsub_rn(ev.x, f0);
                float d1 = __fsub_rn(ev.y, f1);
                float d2 = __fsub_rn(ev.z, f2);
                float d3 = __fsub_rn(ev.w, f3);
                ldist = __fadd_rn(ldist, __fmul_rn(d0, d0));
                ldist = __fadd_rn(ldist, __fmul_rn(d1, d1));
                ldist = __fadd_rn(ldist, __fmul_rn(d2, d2));
                ldist = __fadd_rn(ldist, __fmul_rn(d3, d3));
                outp[(4 * q + 0) * HWC] = __fadd_rn(f0, d0);
                outp[(4 * q + 1) * HWC] = __fadd_rn(f1, d1);
                outp[(4 * q + 2) * HWC] = __fadd_rn(f2, d2);
                outp[(4 * q + 3) * HWC] = __fadd_rn(f3, d3);
            }
        }
        __syncthreads();            // wl dead; red overlay now safe

        // ---- per-tile deterministic tree reduce -> g_part[tile] ----
        red[tid] = ldist;
        __syncthreads();
        #pragma unroll
        for (int s = TPB / 2; s > 0; s >>= 1) {
            if (tid < s) red[tid] += red[tid + s];
            __syncthreads();
        }
        if (tid == 0) g_part[tile] = red[0];
        __syncthreads();
    }

    // ---- grid finalize: last CTA reduces the 1024 tile partials ----
    __shared__ unsigned s_last;
    __threadfence();
    if (tid == 0) s_last = (atomicAdd(&g_done, 1u) == GRIDP - 1u);
    __syncthreads();

    if (s_last) {
        red[tid] = (g_part[tid] + g_part[tid + 256])
                 + (g_part[tid + 512] + g_part[tid + 768]);
        __syncthreads();
        #pragma unroll
        for (int s = TPB / 2; s > 0; s >>= 1) {
            if (tid < s) red[tid] += red[tid + s];
            __syncthreads();
        }
        if (tid == 0) {
            float m = red[0] / 8388608.0f;                   // exact /2^23
            *loss_out = __fadd_rn(__fmul_rn(m, 0.25f), m);   // fl(0.25m)+m
            g_done = 0;
            g_tile = 0;                                      // reset for replay
        }
    }
}

extern "C" void kernel_launch(void* const* d_in, const int* in_sizes, int n_in,
                              void* d_out, int out_size) {
    const float* latents   = (const float*)d_in[0];   // [32,64,64,64] fp32
    const float* embedding = (const float*)d_in[1];   // [512,64] fp32
    float* out  = (float*)d_out;                      // tensor, then loss scalar
    float* loss = out + (out_size - 1);

    cudaFuncSetAttribute(vq_kernel, cudaFuncAttributeMaxDynamicSharedMemorySize, SMEM_BYTES);
    vq_kernel<<<GRIDP, TPB, SMEM_BYTES>>>(latents, embedding, out, loss);
}